// round 16
// baseline (speedup 1.0000x reference)
#include <cuda_runtime.h>
#include <cuda_fp16.h>
#include <math.h>
#include <stdint.h>

// ---------------------------------------------------------------------------
// Problem dims
#define Bdim 4096
#define Hdim 2048
#define Ndim 8192   // 4*H
#define Kdim 2048

// GEMM tiling: BK=64, 3 stages, 2 CTAs/SM  (at tensor-pipe floor — do not touch)
#define BM 128
#define BN 128
#define BK 64
#define STAGES 3
#define NT (Kdim / BK)      // 32

#define RSB  144
#define STG_A 0
#define STG_B 18432
#define STG_SIZE 36864
#define SMEM_TOTAL (STAGES * STG_SIZE)   // 110592 per CTA -> 2 CTAs/SM

// Scratch (static device arrays; no runtime allocation allowed)
__device__ __half g_zh[(size_t)Bdim * Ndim];   // z in fp16 (64 MB)
__device__ __half g_Ah[(size_t)Bdim * Kdim];
__device__ __half g_Bh[(size_t)Ndim * Kdim];

// ---------------------------------------------------------------------------
__device__ __forceinline__ uint32_t smem_u32(const void* p) {
    uint32_t a;
    asm("{ .reg .u64 t; cvta.to.shared.u64 t, %1; cvt.u32.u64 %0, t; }" : "=r"(a) : "l"(p));
    return a;
}
__device__ __forceinline__ void cp16(uint32_t dst, const void* src) {
    asm volatile("cp.async.cg.shared.global [%0], [%1], 16;\n" :: "r"(dst), "l"(src) : "memory");
}
#define CP_COMMIT()  asm volatile("cp.async.commit_group;" ::: "memory")
#define CP_WAIT(n)   asm volatile("cp.async.wait_group %0;" :: "n"(n) : "memory")

#define LDSM4(r0, r1, r2, r3, addr)                                           \
    asm volatile("ldmatrix.sync.aligned.m8n8.x4.shared.b16 {%0,%1,%2,%3},[%4];" \
        : "=r"(r0), "=r"(r1), "=r"(r2), "=r"(r3) : "r"(addr))

#define MMA_F16(d, a, b0, b1)                                                 \
    asm volatile("mma.sync.aligned.m16n8k16.row.col.f32.f16.f16.f32 "         \
        "{%0,%1,%2,%3},{%4,%5,%6,%7},{%8,%9},{%0,%1,%2,%3};"                  \
        : "+f"((d)[0]), "+f"((d)[1]), "+f"((d)[2]), "+f"((d)[3])              \
        : "r"((a)[0]), "r"((a)[1]), "r"((a)[2]), "r"((a)[3]),                 \
          "r"(b0), "r"(b1))

// ---------------------------------------------------------------------------
// Kernel 0: fused fp32 -> fp16 conversion, 4 independent float4 per iteration
// (MLP=4, grid 2048 — measured-optimal). Evict-first source reads.
// ---------------------------------------------------------------------------
#define NA4 (Bdim * Kdim / 4)          // 2M float4
#define NB4 (Ndim * Kdim / 4)          // 4M float4
#define NT4 (NA4 + NB4)                // 6M float4 total
__device__ __forceinline__ float4 ldcs4(const float4* p) {
    float4 v;
    asm volatile("ld.global.cs.v4.f32 {%0,%1,%2,%3}, [%4];"
                 : "=f"(v.x), "=f"(v.y), "=f"(v.z), "=f"(v.w) : "l"(p));
    return v;
}
__device__ __forceinline__ uint4 ldcs4u(const uint4* p) {
    uint4 v;
    asm volatile("ld.global.cs.v4.u32 {%0,%1,%2,%3}, [%4];"
                 : "=r"(v.x), "=r"(v.y), "=r"(v.z), "=r"(v.w) : "l"(p));
    return v;
}
__global__ __launch_bounds__(256) void cvt_fused_kernel(
    const float* __restrict__ ha, const float* __restrict__ wb,
    __half* __restrict__ Ah, __half* __restrict__ Bh)
{
    const int quarter = NT4 / 4;       // 1.5M chunks
    const int base = blockIdx.x * blockDim.x + threadIdx.x;
    const int width = gridDim.x * blockDim.x;

    for (int i0 = base; i0 < quarter; i0 += width) {
        float4 v[4];
#pragma unroll
        for (int q = 0; q < 4; q++) {
            const int i = i0 + q * quarter;
            v[q] = (i < NA4) ? ldcs4((const float4*)ha + i)
                             : ldcs4((const float4*)wb + (i - NA4));
        }
#pragma unroll
        for (int q = 0; q < 4; q++) {
            const int i = i0 + q * quarter;
            __half2 a, b;
            a.x = __float2half_rn(v[q].x); a.y = __float2half_rn(v[q].y);
            b.x = __float2half_rn(v[q].z); b.y = __float2half_rn(v[q].w);
            __half* dst = (i < NA4) ? Ah : Bh;
            const int j = (i < NA4) ? i : i - NA4;
            ((__half2*)dst)[2 * j]     = a;
            ((__half2*)dst)[2 * j + 1] = b;
        }
    }
}

// ---------------------------------------------------------------------------
// Kernel 1: z[M,N] = A[M,K] @ B[N,K]^T + bias   (fp16 in, fp32 accum, fp16 out)
// cp.async pipeline (async loads are load-bearing: keep off the reg scoreboard)
// ---------------------------------------------------------------------------
__global__ __launch_bounds__(256, 2) void gemm_tc_kernel(
    const __half* __restrict__ A, const __half* __restrict__ B,
    const float* __restrict__ bias, __half* __restrict__ Z)
{
    extern __shared__ char smem[];
    const uint32_t sb = smem_u32(smem);

    const int tid    = threadIdx.x;
    const int lane   = tid & 31;
    const int wid    = tid >> 5;
    const int warp_m = wid & 1;
    const int warp_n = wid >> 1;
    const int bm     = blockIdx.y * BM;
    const int bn     = blockIdx.x * BN;

    const char* Ag = (const char*)(A + (size_t)bm * Kdim);
    const char* Bg = (const char*)(B + (size_t)bn * Kdim);

    const int lc = (tid & 7) * 16;
    const int lr = tid >> 3;

    uint32_t offA[4];
#pragma unroll
    for (int mt = 0; mt < 4; mt++)
        offA[mt] = (uint32_t)((warp_m * 64 + mt * 16 + (lane & 15)) * RSB + (lane >> 4) * 16);
    uint32_t offB[2];
#pragma unroll
    for (int pr = 0; pr < 2; pr++)
        offB[pr] = (uint32_t)((warp_n * 32 + pr * 16 + (lane & 7) + ((lane >> 4) & 1) * 8) * RSB
                              + ((lane >> 3) & 1) * 16);

    float acc[4][4][4];
#pragma unroll
    for (int mt = 0; mt < 4; mt++)
#pragma unroll
        for (int nt = 0; nt < 4; nt++)
#pragma unroll
            for (int q = 0; q < 4; q++) acc[mt][nt][q] = 0.f;

#pragma unroll
    for (int t = 0; t < STAGES - 1; t++) {
        const uint32_t st = sb + t * STG_SIZE;
        const size_t kb = (size_t)t * (BK * 2);
#pragma unroll
        for (int p = 0; p < 4; p++) {
            const int r = lr + p * 32;
            cp16(st + STG_A + r * RSB + lc, Ag + (size_t)r * (Kdim * 2) + kb + lc);
            cp16(st + STG_B + r * RSB + lc, Bg + (size_t)r * (Kdim * 2) + kb + lc);
        }
        CP_COMMIT();
    }

    for (int t = 0; t < NT; t++) {
        CP_WAIT(STAGES - 2);
        __syncthreads();

        const int tn = t + STAGES - 1;
        if (tn < NT) {
            const uint32_t st = sb + (tn % STAGES) * STG_SIZE;
            const size_t kb = (size_t)tn * (BK * 2);
#pragma unroll
            for (int p = 0; p < 4; p++) {
                const int r = lr + p * 32;
                cp16(st + STG_A + r * RSB + lc, Ag + (size_t)r * (Kdim * 2) + kb + lc);
                cp16(st + STG_B + r * RSB + lc, Bg + (size_t)r * (Kdim * 2) + kb + lc);
            }
        }
        CP_COMMIT();

        const uint32_t st = sb + (t % STAGES) * STG_SIZE;
#pragma unroll
        for (int ks = 0; ks < 4; ks++) {
            const uint32_t ko = ks * 32;
            uint32_t ah[4][4];
#pragma unroll
            for (int mt = 0; mt < 4; mt++)
                LDSM4(ah[mt][0], ah[mt][1], ah[mt][2], ah[mt][3], st + STG_A + offA[mt] + ko);
#pragma unroll
            for (int pr = 0; pr < 2; pr++) {
                uint32_t bh[4];
                LDSM4(bh[0], bh[1], bh[2], bh[3], st + STG_B + offB[pr] + ko);
#pragma unroll
                for (int sub = 0; sub < 2; sub++) {
                    const int nt = pr * 2 + sub;
#pragma unroll
                    for (int mt = 0; mt < 4; mt++)
                        MMA_F16(acc[mt][nt], ah[mt], bh[2 * sub], bh[2 * sub + 1]);
                }
            }
        }
    }

    const int ln4 = lane >> 2;
    const int lq  = lane & 3;
#pragma unroll
    for (int mt = 0; mt < 4; mt++) {
#pragma unroll
        for (int nt = 0; nt < 4; nt++) {
            const int m0 = bm + warp_m * 64 + mt * 16 + ln4;
            const int n  = bn + warp_n * 32 + nt * 8 + lq * 2;
            const float2 bv = *(const float2*)(bias + n);
            __half2 o0 = __floats2half2_rn(acc[mt][nt][0] + bv.x, acc[mt][nt][1] + bv.y);
            __half2 o1 = __floats2half2_rn(acc[mt][nt][2] + bv.x, acc[mt][nt][3] + bv.y);
            *(__half2*)(Z + (size_t)m0 * Ndim + n)       = o0;
            *(__half2*)(Z + (size_t)(m0 + 8) * Ndim + n) = o1;
        }
    }
}

// ---------------------------------------------------------------------------
// Kernel 2: per-row GroupNorm + LSTM gates, fp16 z, HW tanh.approx,
// evict-first loads for single-use z/c streams, streaming (.cs) output stores
// ---------------------------------------------------------------------------
__device__ __forceinline__ float tanh_fast(float x) {
    float y;
    asm("tanh.approx.f32 %0, %1;" : "=f"(y) : "f"(x));
    return y;
}
__device__ __forceinline__ float sigmoid_fast(float x) {
    return fmaf(tanh_fast(0.5f * x), 0.5f, 0.5f);
}
__device__ __forceinline__ void stcs4(float4* p, float4 v) {
    asm volatile("st.global.cs.v4.f32 [%0], {%1,%2,%3,%4};"
                 :: "l"(p), "f"(v.x), "f"(v.y), "f"(v.z), "f"(v.w) : "memory");
}

__global__ __launch_bounds__(256) void gn_gates_kernel(
    const __half* __restrict__ z, const float* __restrict__ cin,
    const float* __restrict__ gw, const float* __restrict__ gb,
    float* __restrict__ out)
{
    __shared__ uint4 zs[1024];           // full z row in fp16 (16 KB)
    __shared__ float red_s[8], red_q[8];
    __shared__ float s_mean[4], s_rstd[4];

    const int r = blockIdx.x;
    const int t = threadIdx.x;
    const uint4* z8 = (const uint4*)(z + (size_t)r * Ndim);

    const float* crow = cin + (size_t)r * Hdim;
    if (t < 64)
        asm volatile("prefetch.global.L2 [%0];" :: "l"(crow + t * 32));

    const int g    = t >> 6;
    const int lane = t & 63;
    float s = 0.f, ss = 0.f;
#pragma unroll
    for (int i = 0; i < 4; i++) {
        const int idx = g * 256 + lane + i * 64;
        uint4 v = ldcs4u(z8 + idx);      // single-use: evict-first
        zs[idx] = v;
        const __half2* hp = (const __half2*)&v;
#pragma unroll
        for (int q = 0; q < 4; q++) {
            float2 f = __half22float2(hp[q]);
            s  += f.x + f.y;
            ss += f.x * f.x + f.y * f.y;
        }
    }
#pragma unroll
    for (int off = 16; off >= 1; off >>= 1) {
        s  += __shfl_xor_sync(0xffffffffu, s,  off);
        ss += __shfl_xor_sync(0xffffffffu, ss, off);
    }
    const int wid = t >> 5;
    if ((t & 31) == 0) { red_s[wid] = s; red_q[wid] = ss; }
    __syncthreads();
    if (t < 4) {
        float m = (red_s[2 * t] + red_s[2 * t + 1]) * (1.f / 2048.f);
        float v = (red_q[2 * t] + red_q[2 * t + 1]) * (1.f / 2048.f) - m * m;
        s_mean[t] = m;
        s_rstd[t] = rsqrtf(v + 1e-5f);
    }
    __syncthreads();

    const float mi = s_mean[0], ri = s_rstd[0];
    const float mf = s_mean[1], rf = s_rstd[1];
    const float mo = s_mean[2], ro = s_rstd[2];
    const float mg = s_mean[3], rg = s_rstd[3];

    const float4* c4  = (const float4*)crow;
    const float4* gw4 = (const float4*)gw;
    const float4* gb4 = (const float4*)gb;
    float4* h4  = (float4*)out + (size_t)r * (Hdim / 4);
    float4* cn4 = (float4*)out + (size_t)Bdim * (Hdim / 4) + (size_t)r * (Hdim / 4);
    const uint2* zs2 = (const uint2*)zs;

#pragma unroll
    for (int p = 0; p < 2; p++) {
        const int j4 = t + p * 256;
        uint2 pi = zs2[j4];
        uint2 pf = zs2[512 + j4];
        uint2 po = zs2[1024 + j4];
        uint2 pg = zs2[1536 + j4];
        float2 zi01 = __half22float2(*(__half2*)&pi.x), zi23 = __half22float2(*(__half2*)&pi.y);
        float2 zf01 = __half22float2(*(__half2*)&pf.x), zf23 = __half22float2(*(__half2*)&pf.y);
        float2 zo01 = __half22float2(*(__half2*)&po.x), zo23 = __half22float2(*(__half2*)&po.y);
        float2 zg01 = __half22float2(*(__half2*)&pg.x), zg23 = __half22float2(*(__half2*)&pg.y);
        float4 zi = make_float4(zi01.x, zi01.y, zi23.x, zi23.y);
        float4 zf = make_float4(zf01.x, zf01.y, zf23.x, zf23.y);
        float4 zo = make_float4(zo01.x, zo01.y, zo23.x, zo23.y);
        float4 zg = make_float4(zg01.x, zg01.y, zg23.x, zg23.y);

        float4 wi = gw4[j4],        bi  = gb4[j4];
        float4 wf = gw4[512 + j4],  bf2 = gb4[512 + j4];
        float4 wo = gw4[1024 + j4], bo  = gb4[1024 + j4];
        float4 wg = gw4[1536 + j4], bg  = gb4[1536 + j4];
        float4 cv = ldcs4(c4 + j4);      // single-use: evict-first

        float4 hn, cn;
#define GATE(comp)                                                            \
        {                                                                     \
            float vi = (zi.comp - mi) * ri * wi.comp + bi.comp;               \
            float vf = (zf.comp - mf) * rf * wf.comp + bf2.comp;              \
            float vo = (zo.comp - mo) * ro * wo.comp + bo.comp;               \
            float vg = (zg.comp - mg) * rg * wg.comp + bg.comp;               \
            float cnew = sigmoid_fast(vf) * cv.comp                           \
                       + sigmoid_fast(vi) * tanh_fast(vg);                    \
            cn.comp = cnew;                                                   \
            hn.comp = sigmoid_fast(vo) * tanh_fast(cnew);                     \
        }
        GATE(x); GATE(y); GATE(z); GATE(w);
#undef GATE
        stcs4(&h4[j4],  hn);
        stcs4(&cn4[j4], cn);
    }
}

// ---------------------------------------------------------------------------
extern "C" void kernel_launch(void* const* d_in, const int* in_sizes, int n_in,
                              void* d_out, int out_size)
{
    // metadata order: x(0, unused), h(1), c(2), W(3), b(4), gn_weight(5), gn_bias(6)
    const float* h  = (const float*)d_in[1];
    const float* c  = (const float*)d_in[2];
    const float* W  = (const float*)d_in[3];
    const float* b  = (const float*)d_in[4];
    const float* gw = (const float*)d_in[5];
    const float* gb = (const float*)d_in[6];
    float* out = (float*)d_out;

    __half *z, *Ah, *Bh;
    cudaGetSymbolAddress((void**)&z,  g_zh);
    cudaGetSymbolAddress((void**)&Ah, g_Ah);
    cudaGetSymbolAddress((void**)&Bh, g_Bh);

    cudaFuncSetAttribute(gemm_tc_kernel,
                         cudaFuncAttributeMaxDynamicSharedMemorySize, SMEM_TOTAL);

    cvt_fused_kernel<<<2048, 256>>>(h, W, Ah, Bh);

    dim3 ggrid(Ndim / BN, Bdim / BM);   // (64, 32)
    gemm_tc_kernel<<<ggrid, 256, SMEM_TOTAL>>>(Ah, Bh, b, z);

    gn_gates_kernel<<<Bdim, 256>>>(z, c, gw, gb, out);
}

// round 17
// speedup vs baseline: 1.0043x; 1.0043x over previous
#include <cuda_runtime.h>
#include <cuda_fp16.h>
#include <math.h>
#include <stdint.h>

// ---------------------------------------------------------------------------
// Problem dims
#define Bdim 4096
#define Hdim 2048
#define Ndim 8192   // 4*H
#define Kdim 2048

// GEMM tiling: BK=64, 3 stages, 2 CTAs/SM  (at tensor-pipe floor — do not touch)
#define BM 128
#define BN 128
#define BK 64
#define STAGES 3
#define NT (Kdim / BK)      // 32

#define RSB  144
#define STG_A 0
#define STG_B 18432
#define STG_SIZE 36864
#define SMEM_TOTAL (STAGES * STG_SIZE)   // 110592 per CTA -> 2 CTAs/SM

// Scratch (static device arrays; no runtime allocation allowed)
__device__ __half g_zh[(size_t)Bdim * Ndim];   // z in fp16 (64 MB)
__device__ __half g_Ah[(size_t)Bdim * Kdim];
__device__ __half g_Bh[(size_t)Ndim * Kdim];

// ---------------------------------------------------------------------------
__device__ __forceinline__ uint32_t smem_u32(const void* p) {
    uint32_t a;
    asm("{ .reg .u64 t; cvta.to.shared.u64 t, %1; cvt.u32.u64 %0, t; }" : "=r"(a) : "l"(p));
    return a;
}
__device__ __forceinline__ void cp16(uint32_t dst, const void* src) {
    asm volatile("cp.async.cg.shared.global [%0], [%1], 16;\n" :: "r"(dst), "l"(src) : "memory");
}
#define CP_COMMIT()  asm volatile("cp.async.commit_group;" ::: "memory")
#define CP_WAIT(n)   asm volatile("cp.async.wait_group %0;" :: "n"(n) : "memory")

#define LDSM4(r0, r1, r2, r3, addr)                                           \
    asm volatile("ldmatrix.sync.aligned.m8n8.x4.shared.b16 {%0,%1,%2,%3},[%4];" \
        : "=r"(r0), "=r"(r1), "=r"(r2), "=r"(r3) : "r"(addr))

#define MMA_F16(d, a, b0, b1)                                                 \
    asm volatile("mma.sync.aligned.m16n8k16.row.col.f32.f16.f16.f32 "         \
        "{%0,%1,%2,%3},{%4,%5,%6,%7},{%8,%9},{%0,%1,%2,%3};"                  \
        : "+f"((d)[0]), "+f"((d)[1]), "+f"((d)[2]), "+f"((d)[3])              \
        : "r"((a)[0]), "r"((a)[1]), "r"((a)[2]), "r"((a)[3]),                 \
          "r"(b0), "r"(b1))

// ---------------------------------------------------------------------------
// Kernel 0: fused fp32 -> fp16 conversion, 4 independent float4 per iteration
// (MLP=4, grid 2048 — the measured-optimal point). Evict-first source reads.
// ---------------------------------------------------------------------------
#define NA4 (Bdim * Kdim / 4)          // 2M float4
#define NB4 (Ndim * Kdim / 4)          // 4M float4
#define NT4 (NA4 + NB4)                // 6M float4 total
__device__ __forceinline__ float4 ldcs4(const float4* p) {
    float4 v;
    asm volatile("ld.global.cs.v4.f32 {%0,%1,%2,%3}, [%4];"
                 : "=f"(v.x), "=f"(v.y), "=f"(v.z), "=f"(v.w) : "l"(p));
    return v;
}
__global__ __launch_bounds__(256) void cvt_fused_kernel(
    const float* __restrict__ ha, const float* __restrict__ wb,
    __half* __restrict__ Ah, __half* __restrict__ Bh)
{
    const int quarter = NT4 / 4;       // 1.5M chunks
    const int base = blockIdx.x * blockDim.x + threadIdx.x;
    const int width = gridDim.x * blockDim.x;

    for (int i0 = base; i0 < quarter; i0 += width) {
        float4 v[4];
#pragma unroll
        for (int q = 0; q < 4; q++) {
            const int i = i0 + q * quarter;
            v[q] = (i < NA4) ? ldcs4((const float4*)ha + i)
                             : ldcs4((const float4*)wb + (i - NA4));
        }
#pragma unroll
        for (int q = 0; q < 4; q++) {
            const int i = i0 + q * quarter;
            __half2 a, b;
            a.x = __float2half_rn(v[q].x); a.y = __float2half_rn(v[q].y);
            b.x = __float2half_rn(v[q].z); b.y = __float2half_rn(v[q].w);
            __half* dst = (i < NA4) ? Ah : Bh;
            const int j = (i < NA4) ? i : i - NA4;
            ((__half2*)dst)[2 * j]     = a;
            ((__half2*)dst)[2 * j + 1] = b;
        }
    }
}

// ---------------------------------------------------------------------------
// Kernel 1: z[M,N] = A[M,K] @ B[N,K]^T + bias   (fp16 in, fp32 accum, fp16 out)
// cp.async pipeline (async loads are load-bearing: keep off the reg scoreboard)
// ---------------------------------------------------------------------------
__global__ __launch_bounds__(256, 2) void gemm_tc_kernel(
    const __half* __restrict__ A, const __half* __restrict__ B,
    const float* __restrict__ bias, __half* __restrict__ Z)
{
    extern __shared__ char smem[];
    const uint32_t sb = smem_u32(smem);

    const int tid    = threadIdx.x;
    const int lane   = tid & 31;
    const int wid    = tid >> 5;
    const int warp_m = wid & 1;
    const int warp_n = wid >> 1;
    const int bm     = blockIdx.y * BM;
    const int bn     = blockIdx.x * BN;

    const char* Ag = (const char*)(A + (size_t)bm * Kdim);
    const char* Bg = (const char*)(B + (size_t)bn * Kdim);

    const int lc = (tid & 7) * 16;
    const int lr = tid >> 3;

    uint32_t offA[4];
#pragma unroll
    for (int mt = 0; mt < 4; mt++)
        offA[mt] = (uint32_t)((warp_m * 64 + mt * 16 + (lane & 15)) * RSB + (lane >> 4) * 16);
    uint32_t offB[2];
#pragma unroll
    for (int pr = 0; pr < 2; pr++)
        offB[pr] = (uint32_t)((warp_n * 32 + pr * 16 + (lane & 7) + ((lane >> 4) & 1) * 8) * RSB
                              + ((lane >> 3) & 1) * 16);

    float acc[4][4][4];
#pragma unroll
    for (int mt = 0; mt < 4; mt++)
#pragma unroll
        for (int nt = 0; nt < 4; nt++)
#pragma unroll
            for (int q = 0; q < 4; q++) acc[mt][nt][q] = 0.f;

#pragma unroll
    for (int t = 0; t < STAGES - 1; t++) {
        const uint32_t st = sb + t * STG_SIZE;
        const size_t kb = (size_t)t * (BK * 2);
#pragma unroll
        for (int p = 0; p < 4; p++) {
            const int r = lr + p * 32;
            cp16(st + STG_A + r * RSB + lc, Ag + (size_t)r * (Kdim * 2) + kb + lc);
            cp16(st + STG_B + r * RSB + lc, Bg + (size_t)r * (Kdim * 2) + kb + lc);
        }
        CP_COMMIT();
    }

    for (int t = 0; t < NT; t++) {
        CP_WAIT(STAGES - 2);
        __syncthreads();

        const int tn = t + STAGES - 1;
        if (tn < NT) {
            const uint32_t st = sb + (tn % STAGES) * STG_SIZE;
            const size_t kb = (size_t)tn * (BK * 2);
#pragma unroll
            for (int p = 0; p < 4; p++) {
                const int r = lr + p * 32;
                cp16(st + STG_A + r * RSB + lc, Ag + (size_t)r * (Kdim * 2) + kb + lc);
                cp16(st + STG_B + r * RSB + lc, Bg + (size_t)r * (Kdim * 2) + kb + lc);
            }
        }
        CP_COMMIT();

        const uint32_t st = sb + (t % STAGES) * STG_SIZE;
#pragma unroll
        for (int ks = 0; ks < 4; ks++) {
            const uint32_t ko = ks * 32;
            uint32_t ah[4][4];
#pragma unroll
            for (int mt = 0; mt < 4; mt++)
                LDSM4(ah[mt][0], ah[mt][1], ah[mt][2], ah[mt][3], st + STG_A + offA[mt] + ko);
#pragma unroll
            for (int pr = 0; pr < 2; pr++) {
                uint32_t bh[4];
                LDSM4(bh[0], bh[1], bh[2], bh[3], st + STG_B + offB[pr] + ko);
#pragma unroll
                for (int sub = 0; sub < 2; sub++) {
                    const int nt = pr * 2 + sub;
#pragma unroll
                    for (int mt = 0; mt < 4; mt++)
                        MMA_F16(acc[mt][nt], ah[mt], bh[2 * sub], bh[2 * sub + 1]);
                }
            }
        }
    }

    const int ln4 = lane >> 2;
    const int lq  = lane & 3;
#pragma unroll
    for (int mt = 0; mt < 4; mt++) {
#pragma unroll
        for (int nt = 0; nt < 4; nt++) {
            const int m0 = bm + warp_m * 64 + mt * 16 + ln4;
            const int n  = bn + warp_n * 32 + nt * 8 + lq * 2;
            const float2 bv = *(const float2*)(bias + n);
            __half2 o0 = __floats2half2_rn(acc[mt][nt][0] + bv.x, acc[mt][nt][1] + bv.y);
            __half2 o1 = __floats2half2_rn(acc[mt][nt][2] + bv.x, acc[mt][nt][3] + bv.y);
            *(__half2*)(Z + (size_t)m0 * Ndim + n)       = o0;
            *(__half2*)(Z + (size_t)(m0 + 8) * Ndim + n) = o1;
        }
    }
}

// ---------------------------------------------------------------------------
// Kernel 2: per-row GroupNorm + LSTM gates, fp16 z, HW tanh.approx,
// streaming (.cs) output stores; z/c reads use default policy (L2 hits from GEMM)
// ---------------------------------------------------------------------------
__device__ __forceinline__ float tanh_fast(float x) {
    float y;
    asm("tanh.approx.f32 %0, %1;" : "=f"(y) : "f"(x));
    return y;
}
__device__ __forceinline__ float sigmoid_fast(float x) {
    return fmaf(tanh_fast(0.5f * x), 0.5f, 0.5f);
}
__device__ __forceinline__ void stcs4(float4* p, float4 v) {
    asm volatile("st.global.cs.v4.f32 [%0], {%1,%2,%3,%4};"
                 :: "l"(p), "f"(v.x), "f"(v.y), "f"(v.z), "f"(v.w) : "memory");
}

__global__ __launch_bounds__(256) void gn_gates_kernel(
    const __half* __restrict__ z, const float* __restrict__ cin,
    const float* __restrict__ gw, const float* __restrict__ gb,
    float* __restrict__ out)
{
    __shared__ uint4 zs[1024];           // full z row in fp16 (16 KB)
    __shared__ float red_s[8], red_q[8];
    __shared__ float s_mean[4], s_rstd[4];

    const int r = blockIdx.x;
    const int t = threadIdx.x;
    const uint4* z8 = (const uint4*)(z + (size_t)r * Ndim);

    const float* crow = cin + (size_t)r * Hdim;
    if (t < 64)
        asm volatile("prefetch.global.L2 [%0];" :: "l"(crow + t * 32));

    const int g    = t >> 6;
    const int lane = t & 63;
    float s = 0.f, ss = 0.f;
#pragma unroll
    for (int i = 0; i < 4; i++) {
        const int idx = g * 256 + lane + i * 64;
        uint4 v = z8[idx];
        zs[idx] = v;
        const __half2* hp = (const __half2*)&v;
#pragma unroll
        for (int q = 0; q < 4; q++) {
            float2 f = __half22float2(hp[q]);
            s  += f.x + f.y;
            ss += f.x * f.x + f.y * f.y;
        }
    }
#pragma unroll
    for (int off = 16; off >= 1; off >>= 1) {
        s  += __shfl_xor_sync(0xffffffffu, s,  off);
        ss += __shfl_xor_sync(0xffffffffu, ss, off);
    }
    const int wid = t >> 5;
    if ((t & 31) == 0) { red_s[wid] = s; red_q[wid] = ss; }
    __syncthreads();
    if (t < 4) {
        float m = (red_s[2 * t] + red_s[2 * t + 1]) * (1.f / 2048.f);
        float v = (red_q[2 * t] + red_q[2 * t + 1]) * (1.f / 2048.f) - m * m;
        s_mean[t] = m;
        s_rstd[t] = rsqrtf(v + 1e-5f);
    }
    __syncthreads();

    const float mi = s_mean[0], ri = s_rstd[0];
    const float mf = s_mean[1], rf = s_rstd[1];
    const float mo = s_mean[2], ro = s_rstd[2];
    const float mg = s_mean[3], rg = s_rstd[3];

    const float4* c4  = (const float4*)crow;
    const float4* gw4 = (const float4*)gw;
    const float4* gb4 = (const float4*)gb;
    float4* h4  = (float4*)out + (size_t)r * (Hdim / 4);
    float4* cn4 = (float4*)out + (size_t)Bdim * (Hdim / 4) + (size_t)r * (Hdim / 4);
    const uint2* zs2 = (const uint2*)zs;

#pragma unroll
    for (int p = 0; p < 2; p++) {
        const int j4 = t + p * 256;
        uint2 pi = zs2[j4];
        uint2 pf = zs2[512 + j4];
        uint2 po = zs2[1024 + j4];
        uint2 pg = zs2[1536 + j4];
        float2 zi01 = __half22float2(*(__half2*)&pi.x), zi23 = __half22float2(*(__half2*)&pi.y);
        float2 zf01 = __half22float2(*(__half2*)&pf.x), zf23 = __half22float2(*(__half2*)&pf.y);
        float2 zo01 = __half22float2(*(__half2*)&po.x), zo23 = __half22float2(*(__half2*)&po.y);
        float2 zg01 = __half22float2(*(__half2*)&pg.x), zg23 = __half22float2(*(__half2*)&pg.y);
        float4 zi = make_float4(zi01.x, zi01.y, zi23.x, zi23.y);
        float4 zf = make_float4(zf01.x, zf01.y, zf23.x, zf23.y);
        float4 zo = make_float4(zo01.x, zo01.y, zo23.x, zo23.y);
        float4 zg = make_float4(zg01.x, zg01.y, zg23.x, zg23.y);

        float4 wi = gw4[j4],        bi  = gb4[j4];
        float4 wf = gw4[512 + j4],  bf2 = gb4[512 + j4];
        float4 wo = gw4[1024 + j4], bo  = gb4[1024 + j4];
        float4 wg = gw4[1536 + j4], bg  = gb4[1536 + j4];
        float4 cv = c4[j4];

        float4 hn, cn;
#define GATE(comp)                                                            \
        {                                                                     \
            float vi = (zi.comp - mi) * ri * wi.comp + bi.comp;               \
            float vf = (zf.comp - mf) * rf * wf.comp + bf2.comp;              \
            float vo = (zo.comp - mo) * ro * wo.comp + bo.comp;               \
            float vg = (zg.comp - mg) * rg * wg.comp + bg.comp;               \
            float cnew = sigmoid_fast(vf) * cv.comp                           \
                       + sigmoid_fast(vi) * tanh_fast(vg);                    \
            cn.comp = cnew;                                                   \
            hn.comp = sigmoid_fast(vo) * tanh_fast(cnew);                     \
        }
        GATE(x); GATE(y); GATE(z); GATE(w);
#undef GATE
        stcs4(&h4[j4],  hn);
        stcs4(&cn4[j4], cn);
    }
}

// ---------------------------------------------------------------------------
extern "C" void kernel_launch(void* const* d_in, const int* in_sizes, int n_in,
                              void* d_out, int out_size)
{
    // metadata order: x(0, unused), h(1), c(2), W(3), b(4), gn_weight(5), gn_bias(6)
    const float* h  = (const float*)d_in[1];
    const float* c  = (const float*)d_in[2];
    const float* W  = (const float*)d_in[3];
    const float* b  = (const float*)d_in[4];
    const float* gw = (const float*)d_in[5];
    const float* gb = (const float*)d_in[6];
    float* out = (float*)d_out;

    __half *z, *Ah, *Bh;
    cudaGetSymbolAddress((void**)&z,  g_zh);
    cudaGetSymbolAddress((void**)&Ah, g_Ah);
    cudaGetSymbolAddress((void**)&Bh, g_Bh);

    cudaFuncSetAttribute(gemm_tc_kernel,
                         cudaFuncAttributeMaxDynamicSharedMemorySize, SMEM_TOTAL);

    cvt_fused_kernel<<<2048, 256>>>(h, W, Ah, Bh);

    dim3 ggrid(Ndim / BN, Bdim / BM);   // (64, 32)
    gemm_tc_kernel<<<ggrid, 256, SMEM_TOTAL>>>(Ah, Bh, b, z);

    gn_gates_kernel<<<Bdim, 256>>>(z, c, gw, gb, out);
}